// round 1
// baseline (speedup 1.0000x reference)
#include <cuda_runtime.h>
#include <cstdint>

#define N_PTS  400000
#define G_SEG  30000
#define C_IN   64
#define C_OUT  128
#define EPSV   1e-3f

typedef unsigned long long ull;

// ---------------- static device scratch (no runtime allocation) ----------------
__device__ float g_y[(size_t)N_PTS * C_OUT];     // 204.8 MB  post-GEMM (pre-BN1) activations
__device__ float g_seg[(size_t)G_SEG * C_OUT];   // 15.36 MB  segment sums s_g
__device__ int   g_hist[G_SEG];
__device__ int   g_off[G_SEG];
__device__ int   g_cursor[G_SEG];
__device__ int   g_order[N_PTS];
__device__ float g_bn1_sum[C_OUT], g_bn1_sq[C_OUT];
__device__ float g_bn2_sum[C_OUT], g_bn2_sq[C_OUT];
__device__ float g_a1[C_OUT], g_b1[C_OUT];       // BN1 folded affine
__device__ float g_a2[C_OUT], g_b2[C_OUT];       // BN2 folded affine

// ---------------- packed f32x2 helpers (2x FFMA throughput) ----------------
__device__ __forceinline__ ull pack2(float x, float y) {
    ull r; asm("mov.b64 %0, {%1, %2};" : "=l"(r) : "f"(x), "f"(y)); return r;
}
__device__ __forceinline__ void unpack2(ull v, float &x, float &y) {
    asm("mov.b64 {%0, %1}, %2;" : "=f"(x), "=f"(y) : "l"(v));
}
__device__ __forceinline__ void fma2(ull &d, ull a, ull b) {
    asm("fma.rn.f32x2 %0, %1, %2, %0;" : "+l"(d) : "l"(a), "l"(b));
}

// ---------------- float4 helpers ----------------
__device__ __forceinline__ float4 f4add(float4 a, float4 b){ return make_float4(a.x+b.x, a.y+b.y, a.z+b.z, a.w+b.w); }
__device__ __forceinline__ float4 f4sub(float4 a, float4 b){ return make_float4(a.x-b.x, a.y-b.y, a.z-b.z, a.w-b.w); }
__device__ __forceinline__ float4 f4mul(float4 a, float4 b){ return make_float4(a.x*b.x, a.y*b.y, a.z*b.z, a.w*b.w); }
__device__ __forceinline__ float4 f4smul(float s, float4 a){ return make_float4(s*a.x, s*a.y, s*a.z, s*a.w); }
__device__ __forceinline__ float4 f4fma(float4 a, float4 b, float4 c){
    return make_float4(fmaf(a.x,b.x,c.x), fmaf(a.y,b.y,c.y), fmaf(a.z,b.z,c.z), fmaf(a.w,b.w,c.w));
}
__device__ __forceinline__ float4 f4sfma(float s, float4 a, float4 c){
    return make_float4(fmaf(s,a.x,c.x), fmaf(s,a.y,c.y), fmaf(s,a.z,c.z), fmaf(s,a.w,c.w));
}
__device__ __forceinline__ float4 f4zero(){ return make_float4(0.f,0.f,0.f,0.f); }

// ---------------- K0: zero small state ----------------
__global__ void k_init() {
    int i = blockIdx.x * blockDim.x + threadIdx.x;
    if (i < G_SEG) g_hist[i] = 0;
    if (i < C_OUT) { g_bn1_sum[i]=0.f; g_bn1_sq[i]=0.f; g_bn2_sum[i]=0.f; g_bn2_sq[i]=0.f; }
}

// ---------------- K-hist ----------------
__global__ void k_hist(const int* __restrict__ unq, int n) {
    int i = blockIdx.x * blockDim.x + threadIdx.x;
    if (i < n) atomicAdd(&g_hist[unq[i]], 1);
}

// ---------------- K1: GEMM y = X @ W + b  (+ BN1 channel sums) ----------------
// Tile: 128 points x 128 channels, K=64 fully in smem. 256 threads,
// each thread computes 8 points x 8 channels via packed f32x2 FMA.
#define K1_SMEM ((128*65 + 64*128) * 4)
__global__ __launch_bounds__(256, 2) void k1_gemm(
    const float* __restrict__ A, const float* __restrict__ W,
    const float* __restrict__ bias, int n)
{
    extern __shared__ float sm[];
    float* As = sm;              // [128][65] padded
    float* Ws = sm + 128*65;     // [64][128]

    int tid = threadIdx.x;
    int tx = tid & 15;           // channel group: channels tx*8..tx*8+7
    int ty = tid >> 4;           // point group:   points  ty*8..ty*8+7
    int m0 = blockIdx.x * 128;

    // load A tile (128x64 floats)
    #pragma unroll
    for (int it = 0; it < 8; it++) {
        int flat = it*256 + tid;     // float4 units
        int pt = flat >> 4;
        int v  = flat & 15;
        float4 a4 = make_float4(0.f,0.f,0.f,0.f);
        if (m0 + pt < n) a4 = *(const float4*)(A + (size_t)(m0+pt)*C_IN + v*4);
        float* d = As + pt*65 + v*4;
        d[0]=a4.x; d[1]=a4.y; d[2]=a4.z; d[3]=a4.w;
    }
    // load W (64x128 floats)
    #pragma unroll
    for (int it = 0; it < 8; it++) {
        int flat = it*256 + tid;
        ((float4*)Ws)[flat] = __ldg(((const float4*)W) + flat);
    }
    __syncthreads();

    ull acc[8][4];
    #pragma unroll
    for (int r = 0; r < 8; r++)
        #pragma unroll
        for (int c = 0; c < 4; c++) acc[r][c] = 0ull;

    #pragma unroll 8
    for (int k = 0; k < 64; k++) {
        ull ad[8];
        #pragma unroll
        for (int r = 0; r < 8; r++) {
            float a = As[(ty*8 + r)*65 + k];
            ad[r] = pack2(a, a);
        }
        const ull* wrow = (const ull*)(Ws + k*128 + tx*8);
        ull wp0 = wrow[0], wp1 = wrow[1], wp2 = wrow[2], wp3 = wrow[3];
        #pragma unroll
        for (int r = 0; r < 8; r++) {
            fma2(acc[r][0], ad[r], wp0);
            fma2(acc[r][1], ad[r], wp1);
            fma2(acc[r][2], ad[r], wp2);
            fma2(acc[r][3], ad[r], wp3);
        }
    }
    __syncthreads();   // done with As/Ws reads; smem will be reused below

    float bv[8];
    #pragma unroll
    for (int j = 0; j < 8; j++) bv[j] = __ldg(bias + tx*8 + j);

    float psum[8], psq[8];
    #pragma unroll
    for (int j = 0; j < 8; j++) { psum[j] = 0.f; psq[j] = 0.f; }

    #pragma unroll
    for (int r = 0; r < 8; r++) {
        int row = m0 + ty*8 + r;
        float v[8];
        #pragma unroll
        for (int c4 = 0; c4 < 4; c4++) {
            float lo, hi; unpack2(acc[r][c4], lo, hi);
            v[2*c4]   = lo + bv[2*c4];
            v[2*c4+1] = hi + bv[2*c4+1];
        }
        if (row < n) {
            size_t rb = (size_t)row * C_OUT;
            *(float4*)(g_y + rb + tx*8)     = make_float4(v[0],v[1],v[2],v[3]);
            *(float4*)(g_y + rb + tx*8 + 4) = make_float4(v[4],v[5],v[6],v[7]);
            #pragma unroll
            for (int j = 0; j < 8; j++) { psum[j] += v[j]; psq[j] += v[j]*v[j]; }
        }
    }

    // channel-wise reduce across the 16 ty-groups via reused smem
    float* rs = sm;            // [16][128]
    float* rq = sm + 2048;     // [16][128]
    #pragma unroll
    for (int j = 0; j < 8; j++) {
        rs[ty*128 + tx*8 + j] = psum[j];
        rq[ty*128 + tx*8 + j] = psq[j];
    }
    __syncthreads();
    if (tid < 128) {
        float s = 0.f, q = 0.f;
        #pragma unroll
        for (int t = 0; t < 16; t++) { s += rs[t*128 + tid]; q += rq[t*128 + tid]; }
        atomicAdd(&g_bn1_sum[tid], s);
        atomicAdd(&g_bn1_sq[tid], q);
    }
}

// ---------------- K2: single-block scan of hist -> offsets/cursor, + BN1 finalize ----------------
__global__ void k_scan_bn1(const float* __restrict__ g1, const float* __restrict__ be1, int n) {
    int tid = threadIdx.x;
    int lane = tid & 31, wid = tid >> 5;
    const int PER = 30;              // 30 * 1024 >= 30000
    int base = tid * PER;

    int tot = 0;
    for (int j = 0; j < PER; j++) {
        int idx = base + j;
        if (idx < G_SEG) tot += g_hist[idx];
    }
    int x = tot;
    #pragma unroll
    for (int d = 1; d < 32; d <<= 1) {
        int y = __shfl_up_sync(0xffffffffu, x, d);
        if (lane >= d) x += y;
    }
    __shared__ int wsum[32];
    if (lane == 31) wsum[wid] = x;
    __syncthreads();
    if (wid == 0) {
        int v = wsum[lane];
        #pragma unroll
        for (int d = 1; d < 32; d <<= 1) {
            int y = __shfl_up_sync(0xffffffffu, v, d);
            if (lane >= d) v += y;
        }
        wsum[lane] = v;
    }
    __syncthreads();
    int excl = x - tot + (wid ? wsum[wid-1] : 0);

    int run = excl;
    for (int j = 0; j < PER; j++) {
        int idx = base + j;
        if (idx < G_SEG) {
            g_off[idx] = run;
            g_cursor[idx] = run;
            run += g_hist[idx];
        }
    }

    if (tid < C_OUT) {
        float m   = g_bn1_sum[tid] / (float)n;
        float var = g_bn1_sq[tid]  / (float)n - m*m;
        float a   = g1[tid] * rsqrtf(var + EPSV);
        g_a1[tid] = a;
        g_b1[tid] = be1[tid] - m * a;
    }
}

// ---------------- K3: scatter point indices into CSR order ----------------
__global__ void k_scatter(const int* __restrict__ unq, int n) {
    int i = blockIdx.x * blockDim.x + threadIdx.x;
    if (i < n) {
        int g = unq[i];
        int p = atomicAdd(&g_cursor[g], 1);
        g_order[p] = i;
    }
}

// ---------------- K4: gather segment-sum (warp per group) + analytic BN2 stats ----------------
__global__ __launch_bounds__(128) void k4_segsum(
    const float* __restrict__ P,
    const float* __restrict__ Wp1, const float* __restrict__ bp1,
    const float* __restrict__ Wp2, const float* __restrict__ bp2, int n)
{
    int tid = threadIdx.x, lane = tid & 31, w = tid >> 5;
    int warpG = blockIdx.x * 4 + w;
    int nwarp = gridDim.x * 4;

    const float4* W1 = (const float4*)Wp1;
    const float4* W2 = (const float4*)Wp2;
    float4 w10 = __ldg(W1 + lane),      w11 = __ldg(W1 + 32 + lane), w12 = __ldg(W1 + 64 + lane);
    float4 b1v = __ldg((const float4*)bp1 + lane);
    float4 w20 = __ldg(W2 + lane),      w21 = __ldg(W2 + 32 + lane), w22 = __ldg(W2 + 64 + lane);
    float4 b2v = __ldg((const float4*)bp2 + lane);
    float4 a1  = *(const float4*)(g_a1 + lane*4);
    float4 bb1 = *(const float4*)(g_b1 + lane*4);

    float4 accS = f4zero(), accQ = f4zero();   // BN2 sum / sumsq partials (per owned channels)

    for (int g = warpG; g < G_SEG; g += nwarp) {
        int beg = g_off[g];
        int cnt = g_hist[g];
        float4 s = f4zero(), tA = f4zero(), tQ = f4zero();

        int iA = (cnt > 0) ? __ldg(&g_order[beg]) : 0;
        for (int m = 0; m < cnt; m++) {
            int iB = (m + 1 < cnt) ? __ldg(&g_order[beg + m + 1]) : 0;
            float px = floorf(__ldg(P + 3*iA));
            float py = floorf(__ldg(P + 3*iA + 1));
            float pz = floorf(__ldg(P + 3*iA + 2));
            float4 y = *(const float4*)(g_y + (size_t)iA * C_OUT + lane*4);
            float4 feat = f4fma(y, a1, bb1);
            float4 pw1 = f4sfma(px, w10, f4sfma(py, w11, f4sfma(pz, w12, b1v)));
            float4 pw2 = f4sfma(px, w20, f4sfma(py, w21, f4sfma(pz, w22, b2v)));
            float4 a = f4mul(pw2, feat);
            s  = f4fma(pw1, feat, s);
            tA = f4add(tA, a);
            tQ = f4fma(a, a, tQ);
            iA = iB;
        }
        *(float4*)(g_seg + (size_t)g * C_OUT + lane*4) = s;

        float c = (float)cnt;
        // sum_{i in g} out = t_g - cnt*s ;  sum out^2 = tQ - 2 s*t + cnt*s^2
        accS = f4add(accS, f4sub(tA, f4smul(c, s)));
        float4 q = f4sub(tQ, f4smul(2.f, f4mul(s, tA)));
        q = f4fma(s, f4smul(c, s), q);
        accQ = f4add(accQ, q);
    }

    __shared__ float rs[512], rq[512];
    rs[w*128 + lane*4 + 0] = accS.x; rq[w*128 + lane*4 + 0] = accQ.x;
    rs[w*128 + lane*4 + 1] = accS.y; rq[w*128 + lane*4 + 1] = accQ.y;
    rs[w*128 + lane*4 + 2] = accS.z; rq[w*128 + lane*4 + 2] = accQ.z;
    rs[w*128 + lane*4 + 3] = accS.w; rq[w*128 + lane*4 + 3] = accQ.w;
    __syncthreads();
    if (tid < 128) {
        float s = 0.f, q = 0.f;
        #pragma unroll
        for (int t = 0; t < 4; t++) { s += rs[t*128 + tid]; q += rq[t*128 + tid]; }
        atomicAdd(&g_bn2_sum[tid], s);
        atomicAdd(&g_bn2_sq[tid], q);
    }
}

// ---------------- K4b: BN2 finalize ----------------
__global__ void k_bn2fin(const float* __restrict__ g2, const float* __restrict__ be2, int n) {
    int c = threadIdx.x;
    if (c < C_OUT) {
        float m   = g_bn2_sum[c] / (float)n;
        float var = g_bn2_sq[c]  / (float)n - m*m;
        float a   = g2[c] * rsqrtf(var + EPSV);
        g_a2[c] = a;
        g_b2[c] = be2[c] - m * a;
    }
}

// ---------------- K5: final output (warp per point; 4 channels/lane) ----------------
__global__ __launch_bounds__(256) void k5_out(
    const float* __restrict__ P, const int* __restrict__ unq,
    const float* __restrict__ Wp2, const float* __restrict__ bp2,
    float* __restrict__ Out, int n)
{
    int lane = threadIdx.x & 31;
    float4 a1  = *(const float4*)(g_a1 + lane*4);
    float4 bb1 = *(const float4*)(g_b1 + lane*4);
    float4 a2  = *(const float4*)(g_a2 + lane*4);
    float4 bb2 = *(const float4*)(g_b2 + lane*4);
    const float4* W2 = (const float4*)Wp2;
    float4 w20 = __ldg(W2 + lane), w21 = __ldg(W2 + 32 + lane), w22 = __ldg(W2 + 64 + lane);
    float4 b2v = __ldg((const float4*)bp2 + lane);

    long idx = (long)blockIdx.x * blockDim.x + threadIdx.x;
    long total = (long)n * 32;
    if (idx < total) {
        int i = (int)(idx >> 5);
        int g = __ldg(unq + i);
        float px = floorf(__ldg(P + 3*i));
        float py = floorf(__ldg(P + 3*i + 1));
        float pz = floorf(__ldg(P + 3*i + 2));
        float4 y  = *(const float4*)(g_y  + (size_t)i * C_OUT + lane*4);
        float4 sv = *(const float4*)(g_seg + (size_t)g * C_OUT + lane*4);
        float4 feat = f4fma(y, a1, bb1);
        float4 pw2 = f4sfma(px, w20, f4sfma(py, w21, f4sfma(pz, w22, b2v)));
        float4 o = f4sub(f4mul(pw2, feat), sv);
        o = f4fma(o, a2, bb2);
        o.x = fmaxf(o.x, 0.f); o.y = fmaxf(o.y, 0.f);
        o.z = fmaxf(o.z, 0.f); o.w = fmaxf(o.w, 0.f);
        *(float4*)(Out + (size_t)i * C_OUT + lane*4) = o;
    }
}

// ---------------- launch ----------------
extern "C" void kernel_launch(void* const* d_in, const int* in_sizes, int n_in,
                              void* d_out, int out_size)
{
    const float* P    = (const float*)d_in[0];   // points_xyz [N,3]
    const float* X    = (const float*)d_in[1];   // feat_all  [N,64]
    const int*   unq  = (const int*)  d_in[2];   // unq_inv   [N]
    const float* Wpre = (const float*)d_in[3];   // [64,128]
    const float* bpre = (const float*)d_in[4];
    const float* g1   = (const float*)d_in[5];
    const float* be1  = (const float*)d_in[6];
    const float* Wp1  = (const float*)d_in[7];   // [3,128]
    const float* bp1  = (const float*)d_in[8];
    const float* Wp2  = (const float*)d_in[9];   // [3,128]
    const float* bp2  = (const float*)d_in[10];
    const float* g2   = (const float*)d_in[11];
    const float* be2  = (const float*)d_in[12];
    float* Out = (float*)d_out;

    int N = in_sizes[2];

    cudaFuncSetAttribute(k1_gemm, cudaFuncAttributeMaxDynamicSharedMemorySize, K1_SMEM);

    k_init<<<(G_SEG + 255) / 256, 256>>>();
    k_hist<<<(N + 255) / 256, 256>>>(unq, N);
    k1_gemm<<<(N + 127) / 128, 256, K1_SMEM>>>(X, Wpre, bpre, N);
    k_scan_bn1<<<1, 1024>>>(g1, be1, N);
    k_scatter<<<(N + 255) / 256, 256>>>(unq, N);
    k4_segsum<<<1920, 128>>>(P, Wp1, bp1, Wp2, bp2, N);
    k_bn2fin<<<1, 128>>>(g2, be2, N);
    long t5 = (long)N * 32;
    k5_out<<<(int)((t5 + 255) / 256), 256>>>(P, unq, Wp2, bp2, Out, N);
}

// round 2
// speedup vs baseline: 1.2141x; 1.2141x over previous
#include <cuda_runtime.h>
#include <cuda_fp16.h>
#include <cstdint>

#define N_PTS  400000
#define G_SEG  30000
#define C_IN   64
#define C_OUT  128
#define EPSV   1e-3f

typedef unsigned long long ull;

// ---------------- static device scratch (no runtime allocation) ----------------
__device__ __half g_y[(size_t)N_PTS * C_OUT];    // 102.4 MB  post-GEMM (pre-BN1) activations, fp16
__device__ float g_seg[(size_t)G_SEG * C_OUT];   // 15.36 MB  segment sums s_g
__device__ int   g_hist[G_SEG];
__device__ int   g_off[G_SEG];
__device__ int   g_cursor[G_SEG];
__device__ int   g_order[N_PTS];
__device__ int   g_total;
__device__ float g_bn1_sum[C_OUT], g_bn1_sq[C_OUT];
__device__ float g_bn2_sum[C_OUT], g_bn2_sq[C_OUT];
__device__ float g_a1[C_OUT], g_b1[C_OUT];       // BN1 folded affine
__device__ float g_a2[C_OUT], g_b2[C_OUT];       // BN2 folded affine

// ---------------- packed f32x2 helpers (2x FFMA throughput) ----------------
__device__ __forceinline__ ull pack2(float x, float y) {
    ull r; asm("mov.b64 %0, {%1, %2};" : "=l"(r) : "f"(x), "f"(y)); return r;
}
__device__ __forceinline__ void unpack2(ull v, float &x, float &y) {
    asm("mov.b64 {%0, %1}, %2;" : "=f"(x), "=f"(y) : "l"(v));
}
__device__ __forceinline__ void fma2(ull &d, ull a, ull b) {
    asm("fma.rn.f32x2 %0, %1, %2, %0;" : "+l"(d) : "l"(a), "l"(b));
}

// ---------------- float4 helpers ----------------
__device__ __forceinline__ float4 f4add(float4 a, float4 b){ return make_float4(a.x+b.x, a.y+b.y, a.z+b.z, a.w+b.w); }
__device__ __forceinline__ float4 f4sub(float4 a, float4 b){ return make_float4(a.x-b.x, a.y-b.y, a.z-b.z, a.w-b.w); }
__device__ __forceinline__ float4 f4mul(float4 a, float4 b){ return make_float4(a.x*b.x, a.y*b.y, a.z*b.z, a.w*b.w); }
__device__ __forceinline__ float4 f4smul(float s, float4 a){ return make_float4(s*a.x, s*a.y, s*a.z, s*a.w); }
__device__ __forceinline__ float4 f4fma(float4 a, float4 b, float4 c){
    return make_float4(fmaf(a.x,b.x,c.x), fmaf(a.y,b.y,c.y), fmaf(a.z,b.z,c.z), fmaf(a.w,b.w,c.w));
}
__device__ __forceinline__ float4 f4sfma(float s, float4 a, float4 c){
    return make_float4(fmaf(s,a.x,c.x), fmaf(s,a.y,c.y), fmaf(s,a.z,c.z), fmaf(s,a.w,c.w));
}
__device__ __forceinline__ float4 f4zero(){ return make_float4(0.f,0.f,0.f,0.f); }

// load 4 channels (8 bytes fp16) as float4
__device__ __forceinline__ float4 ldy4(const __half* p) {
    uint2 raw = *(const uint2*)p;
    __half2 h0 = *(__half2*)&raw.x;
    __half2 h1 = *(__half2*)&raw.y;
    float2 f0 = __half22float2(h0);
    float2 f1 = __half22float2(h1);
    return make_float4(f0.x, f0.y, f1.x, f1.y);
}

// ---------------- K0: zero small state ----------------
__global__ void k_init() {
    int i = blockIdx.x * blockDim.x + threadIdx.x;
    if (i < G_SEG) g_hist[i] = 0;
    if (i == 0) g_total = 0;
    if (i < C_OUT) { g_bn1_sum[i]=0.f; g_bn1_sq[i]=0.f; g_bn2_sum[i]=0.f; g_bn2_sq[i]=0.f; }
}

// ---------------- K-hist ----------------
__global__ void k_hist(const int* __restrict__ unq, int n) {
    int i = blockIdx.x * blockDim.x + threadIdx.x;
    if (i < n) atomicAdd(&g_hist[unq[i]], 1);
}

// ---------------- K-offsets: unordered CSR offsets via block scan + atomic base ----------------
__global__ __launch_bounds__(256) void k_offsets() {
    int tid = threadIdx.x;
    int g = blockIdx.x * 256 + tid;
    int c = (g < G_SEG) ? g_hist[g] : 0;
    int lane = tid & 31, wid = tid >> 5;

    int x = c;
    #pragma unroll
    for (int d = 1; d < 32; d <<= 1) {
        int y = __shfl_up_sync(0xffffffffu, x, d);
        if (lane >= d) x += y;
    }
    __shared__ int ws[8];
    __shared__ int bbase;
    if (lane == 31) ws[wid] = x;
    __syncthreads();
    if (wid == 0 && lane < 8) {
        int v = ws[lane];
        #pragma unroll
        for (int d = 1; d < 8; d <<= 1) {
            int y = __shfl_up_sync(0xffu, v, d);
            if (lane >= d) v += y;
        }
        ws[lane] = v;
        if (lane == 7) bbase = atomicAdd(&g_total, v);
    }
    __syncthreads();
    int off = bbase + (x - c) + (wid ? ws[wid-1] : 0);
    if (g < G_SEG) { g_off[g] = off; g_cursor[g] = off; }
}

// ---------------- K3: scatter point indices into CSR order ----------------
__global__ void k_scatter(const int* __restrict__ unq, int n) {
    int i = blockIdx.x * blockDim.x + threadIdx.x;
    if (i < n) {
        int g = unq[i];
        int p = atomicAdd(&g_cursor[g], 1);
        g_order[p] = i;
    }
}

// ---------------- K1: GEMM y = X @ W + b  (+ BN1 channel sums), fp16 output ----------------
// Tile: 128 points x 128 channels, K=64 fully in smem. 256 threads,
// each thread computes 8 points x 8 channels via packed f32x2 FMA.
#define K1_SMEM ((128*65 + 64*128) * 4)
__global__ __launch_bounds__(256, 2) void k1_gemm(
    const float* __restrict__ A, const float* __restrict__ W,
    const float* __restrict__ bias, int n)
{
    extern __shared__ float sm[];
    float* As = sm;              // [128][65] padded
    float* Ws = sm + 128*65;     // [64][128]

    int tid = threadIdx.x;
    int tx = tid & 15;           // channel group: channels tx*8..tx*8+7
    int ty = tid >> 4;           // point group:   points  ty*8..ty*8+7
    int m0 = blockIdx.x * 128;

    // load A tile (128x64 floats)
    #pragma unroll
    for (int it = 0; it < 8; it++) {
        int flat = it*256 + tid;     // float4 units
        int pt = flat >> 4;
        int v  = flat & 15;
        float4 a4 = make_float4(0.f,0.f,0.f,0.f);
        if (m0 + pt < n) a4 = *(const float4*)(A + (size_t)(m0+pt)*C_IN + v*4);
        float* d = As + pt*65 + v*4;
        d[0]=a4.x; d[1]=a4.y; d[2]=a4.z; d[3]=a4.w;
    }
    // load W (64x128 floats)
    #pragma unroll
    for (int it = 0; it < 8; it++) {
        int flat = it*256 + tid;
        ((float4*)Ws)[flat] = __ldg(((const float4*)W) + flat);
    }
    __syncthreads();

    ull acc[8][4];
    #pragma unroll
    for (int r = 0; r < 8; r++)
        #pragma unroll
        for (int c = 0; c < 4; c++) acc[r][c] = 0ull;

    #pragma unroll 8
    for (int k = 0; k < 64; k++) {
        ull ad[8];
        #pragma unroll
        for (int r = 0; r < 8; r++) {
            float a = As[(ty*8 + r)*65 + k];
            ad[r] = pack2(a, a);
        }
        const ull* wrow = (const ull*)(Ws + k*128 + tx*8);
        ull wp0 = wrow[0], wp1 = wrow[1], wp2 = wrow[2], wp3 = wrow[3];
        #pragma unroll
        for (int r = 0; r < 8; r++) {
            fma2(acc[r][0], ad[r], wp0);
            fma2(acc[r][1], ad[r], wp1);
            fma2(acc[r][2], ad[r], wp2);
            fma2(acc[r][3], ad[r], wp3);
        }
    }
    __syncthreads();   // done with As/Ws reads; smem reused below

    float bv[8];
    #pragma unroll
    for (int j = 0; j < 8; j++) bv[j] = __ldg(bias + tx*8 + j);

    float psum[8], psq[8];
    #pragma unroll
    for (int j = 0; j < 8; j++) { psum[j] = 0.f; psq[j] = 0.f; }

    #pragma unroll
    for (int r = 0; r < 8; r++) {
        int row = m0 + ty*8 + r;
        float v[8];
        #pragma unroll
        for (int c4 = 0; c4 < 4; c4++) {
            float lo, hi; unpack2(acc[r][c4], lo, hi);
            v[2*c4]   = lo + bv[2*c4];
            v[2*c4+1] = hi + bv[2*c4+1];
        }
        if (row < n) {
            size_t rb = (size_t)row * C_OUT;
            __half2 h[4];
            #pragma unroll
            for (int c4 = 0; c4 < 4; c4++)
                h[c4] = __floats2half2_rn(v[2*c4], v[2*c4+1]);
            *(float4*)(g_y + rb + tx*8) = *(float4*)h;   // 8 halves = 16B
            // BN1 stats on the fp16-rounded values (self-consistent with K4/K5 reads)
            #pragma unroll
            for (int c4 = 0; c4 < 4; c4++) {
                float2 f = __half22float2(h[c4]);
                psum[2*c4]   += f.x;  psq[2*c4]   += f.x*f.x;
                psum[2*c4+1] += f.y;  psq[2*c4+1] += f.y*f.y;
            }
        }
    }

    // channel-wise reduce across the 16 ty-groups via reused smem
    float* rs = sm;            // [16][128]
    float* rq = sm + 2048;     // [16][128]
    #pragma unroll
    for (int j = 0; j < 8; j++) {
        rs[ty*128 + tx*8 + j] = psum[j];
        rq[ty*128 + tx*8 + j] = psq[j];
    }
    __syncthreads();
    if (tid < 128) {
        float s = 0.f, q = 0.f;
        #pragma unroll
        for (int t = 0; t < 16; t++) { s += rs[t*128 + tid]; q += rq[t*128 + tid]; }
        atomicAdd(&g_bn1_sum[tid], s);
        atomicAdd(&g_bn1_sq[tid], q);
    }
}

// ---------------- BN1 finalize ----------------
__global__ void k_bn1fin(const float* __restrict__ g1, const float* __restrict__ be1, int n) {
    int c = threadIdx.x;
    if (c < C_OUT) {
        float m   = g_bn1_sum[c] / (float)n;
        float var = g_bn1_sq[c]  / (float)n - m*m;
        float a   = g1[c] * rsqrtf(var + EPSV);
        g_a1[c] = a;
        g_b1[c] = be1[c] - m * a;
    }
}

// ---------------- K4: gather segment-sum (one warp per group) + analytic BN2 stats ----------------
__global__ __launch_bounds__(128) void k4_segsum(
    const float* __restrict__ P,
    const float* __restrict__ Wp1, const float* __restrict__ bp1,
    const float* __restrict__ Wp2, const float* __restrict__ bp2, int n)
{
    int tid = threadIdx.x, lane = tid & 31, w = tid >> 5;
    int g = blockIdx.x * 4 + w;

    const float4* W1 = (const float4*)Wp1;
    const float4* W2 = (const float4*)Wp2;
    float4 w10 = __ldg(W1 + lane),      w11 = __ldg(W1 + 32 + lane), w12 = __ldg(W1 + 64 + lane);
    float4 b1v = __ldg((const float4*)bp1 + lane);
    float4 w20 = __ldg(W2 + lane),      w21 = __ldg(W2 + 32 + lane), w22 = __ldg(W2 + 64 + lane);
    float4 b2v = __ldg((const float4*)bp2 + lane);
    float4 a1  = *(const float4*)(g_a1 + lane*4);
    float4 bb1 = *(const float4*)(g_b1 + lane*4);

    float4 accS = f4zero(), accQ = f4zero();   // BN2 sum / sumsq partials

    if (g < G_SEG) {
        int beg = g_off[g];
        int cnt = g_hist[g];
        float4 s = f4zero(), tA = f4zero(), tQ = f4zero();

        int iA = (cnt > 0) ? __ldg(&g_order[beg]) : 0;
        for (int m = 0; m < cnt; m++) {
            int iB = (m + 1 < cnt) ? __ldg(&g_order[beg + m + 1]) : 0;
            float px = floorf(__ldg(P + 3*iA));
            float py = floorf(__ldg(P + 3*iA + 1));
            float pz = floorf(__ldg(P + 3*iA + 2));
            float4 y = ldy4(g_y + (size_t)iA * C_OUT + lane*4);
            float4 feat = f4fma(y, a1, bb1);
            float4 pw1 = f4sfma(px, w10, f4sfma(py, w11, f4sfma(pz, w12, b1v)));
            float4 pw2 = f4sfma(px, w20, f4sfma(py, w21, f4sfma(pz, w22, b2v)));
            float4 a = f4mul(pw2, feat);
            s  = f4fma(pw1, feat, s);
            tA = f4add(tA, a);
            tQ = f4fma(a, a, tQ);
            iA = iB;
        }
        *(float4*)(g_seg + (size_t)g * C_OUT + lane*4) = s;

        float c = (float)cnt;
        // sum_{i in g} out = t_g - cnt*s ;  sum out^2 = tQ - 2 s*t + cnt*s^2
        accS = f4add(accS, f4sub(tA, f4smul(c, s)));
        float4 q = f4sub(tQ, f4smul(2.f, f4mul(s, tA)));
        q = f4fma(s, f4smul(c, s), q);
        accQ = f4add(accQ, q);
    }

    __shared__ float rs[512], rq[512];
    rs[w*128 + lane*4 + 0] = accS.x; rq[w*128 + lane*4 + 0] = accQ.x;
    rs[w*128 + lane*4 + 1] = accS.y; rq[w*128 + lane*4 + 1] = accQ.y;
    rs[w*128 + lane*4 + 2] = accS.z; rq[w*128 + lane*4 + 2] = accQ.z;
    rs[w*128 + lane*4 + 3] = accS.w; rq[w*128 + lane*4 + 3] = accQ.w;
    __syncthreads();
    if (tid < 128) {
        float s = 0.f, q = 0.f;
        #pragma unroll
        for (int t = 0; t < 4; t++) { s += rs[t*128 + tid]; q += rq[t*128 + tid]; }
        atomicAdd(&g_bn2_sum[tid], s);
        atomicAdd(&g_bn2_sq[tid], q);
    }
}

// ---------------- BN2 finalize ----------------
__global__ void k_bn2fin(const float* __restrict__ g2, const float* __restrict__ be2, int n) {
    int c = threadIdx.x;
    if (c < C_OUT) {
        float m   = g_bn2_sum[c] / (float)n;
        float var = g_bn2_sq[c]  / (float)n - m*m;
        float a   = g2[c] * rsqrtf(var + EPSV);
        g_a2[c] = a;
        g_b2[c] = be2[c] - m * a;
    }
}

// ---------------- K5: final output (warp per point; 4 channels/lane) ----------------
__global__ __launch_bounds__(256) void k5_out(
    const float* __restrict__ P, const int* __restrict__ unq,
    const float* __restrict__ Wp2, const float* __restrict__ bp2,
    float* __restrict__ Out, int n)
{
    int lane = threadIdx.x & 31;
    float4 a1  = *(const float4*)(g_a1 + lane*4);
    float4 bb1 = *(const float4*)(g_b1 + lane*4);
    float4 a2  = *(const float4*)(g_a2 + lane*4);
    float4 bb2 = *(const float4*)(g_b2 + lane*4);
    const float4* W2 = (const float4*)Wp2;
    float4 w20 = __ldg(W2 + lane), w21 = __ldg(W2 + 32 + lane), w22 = __ldg(W2 + 64 + lane);
    float4 b2v = __ldg((const float4*)bp2 + lane);

    long idx = (long)blockIdx.x * blockDim.x + threadIdx.x;
    long total = (long)n * 32;
    if (idx < total) {
        int i = (int)(idx >> 5);
        int g = __ldg(unq + i);
        float px = floorf(__ldg(P + 3*i));
        float py = floorf(__ldg(P + 3*i + 1));
        float pz = floorf(__ldg(P + 3*i + 2));
        float4 y  = ldy4(g_y + (size_t)i * C_OUT + lane*4);
        float4 sv = *(const float4*)(g_seg + (size_t)g * C_OUT + lane*4);
        float4 feat = f4fma(y, a1, bb1);
        float4 pw2 = f4sfma(px, w20, f4sfma(py, w21, f4sfma(pz, w22, b2v)));
        float4 o = f4sub(f4mul(pw2, feat), sv);
        o = f4fma(o, a2, bb2);
        o.x = fmaxf(o.x, 0.f); o.y = fmaxf(o.y, 0.f);
        o.z = fmaxf(o.z, 0.f); o.w = fmaxf(o.w, 0.f);
        *(float4*)(Out + (size_t)i * C_OUT + lane*4) = o;
    }
}

// ---------------- launch ----------------
extern "C" void kernel_launch(void* const* d_in, const int* in_sizes, int n_in,
                              void* d_out, int out_size)
{
    const float* P    = (const float*)d_in[0];   // points_xyz [N,3]
    const float* X    = (const float*)d_in[1];   // feat_all  [N,64]
    const int*   unq  = (const int*)  d_in[2];   // unq_inv   [N]
    const float* Wpre = (const float*)d_in[3];   // [64,128]
    const float* bpre = (const float*)d_in[4];
    const float* g1   = (const float*)d_in[5];
    const float* be1  = (const float*)d_in[6];
    const float* Wp1  = (const float*)d_in[7];   // [3,128]
    const float* bp1  = (const float*)d_in[8];
    const float* Wp2  = (const float*)d_in[9];   // [3,128]
    const float* bp2  = (const float*)d_in[10];
    const float* g2   = (const float*)d_in[11];
    const float* be2  = (const float*)d_in[12];
    float* Out = (float*)d_out;

    int N = in_sizes[2];

    cudaFuncSetAttribute(k1_gemm, cudaFuncAttributeMaxDynamicSharedMemorySize, K1_SMEM);

    k_init<<<(G_SEG + 255) / 256, 256>>>();
    k_hist<<<(N + 255) / 256, 256>>>(unq, N);
    k_offsets<<<(G_SEG + 255) / 256, 256>>>();
    k_scatter<<<(N + 255) / 256, 256>>>(unq, N);
    k1_gemm<<<(N + 127) / 128, 256, K1_SMEM>>>(X, Wpre, bpre, N);
    k_bn1fin<<<1, 128>>>(g1, be1, N);
    k4_segsum<<<(G_SEG + 3) / 4, 128>>>(P, Wp1, bp1, Wp2, bp2, N);
    k_bn2fin<<<1, 128>>>(g2, be2, N);
    long t5 = (long)N * 32;
    k5_out<<<(int)((t5 + 255) / 256), 256>>>(P, unq, Wp2, bp2, Out, N);
}